// round 1
// baseline (speedup 1.0000x reference)
#include <cuda_runtime.h>

// AdderNet layer: out[n,h,w,f] = sum_{dh,dw,c} |Xpad[n,h+dh,w+dw,c] - filters[f,dh,dw,c]|
// X: [8,32,32,32] f32, filters: [64,3,3,32] f32, out: [8,32,32,64] f32, pad=1, stride=1.

#define N_IMG 8
#define HDIM 32
#define WDIM 32
#define CH 32
#define F_OUT 64
#define KKN 288            // 3*3*32
#define WPAD 34            // w in [-1, 32]

#define XS_ELEMS (3 * CH * WPAD)        // 3264 floats
#define FS_ELEMS (KKN * F_OUT)          // 18432 floats
#define SMEM_BYTES ((XS_ELEMS + FS_ELEMS) * 4)

__device__ __forceinline__ unsigned long long f32x2_add(unsigned long long a,
                                                        unsigned long long b) {
    unsigned long long r;
    asm("add.rn.f32x2 %0, %1, %2;" : "=l"(r) : "l"(a), "l"(b));
    return r;
}

__device__ __forceinline__ unsigned long long pack_dup(float x) {
    unsigned long long r;
    asm("mov.b64 %0, {%1, %1};" : "=l"(r) : "f"(x));
    return r;
}

__global__ __launch_bounds__(256, 2)
void adder_layer_kernel(const float* __restrict__ X,
                        const float* __restrict__ Fw,
                        float* __restrict__ out) {
    extern __shared__ float smem[];
    float* Xs = smem;                 // [3][CH][WPAD]  (row, channel, padded-w)
    float* Fs = smem + XS_ELEMS;      // [KKN][F_OUT]   (negated filters)

    const int tid = threadIdx.x;
    const int n = blockIdx.x >> 5;
    const int h = blockIdx.x & 31;

    // --- Load negated filters: Fs[kk*64 + f] = -Fw[f*288 + kk] ---
    for (int i = tid; i < F_OUT * KKN; i += 256) {
        int f = i / KKN;
        int kk = i - f * KKN;
        Fs[kk * F_OUT + f] = -Fw[i];
    }

    // --- Load 3 input rows, transposed to [c][w], zero-padded ---
    for (int dh = 0; dh < 3; dh++) {
        int row = h - 1 + dh;
        for (int i = tid; i < CH * WPAD; i += 256) {
            // i = wp*CH + c for coalesced global reads (c fastest)
            int wp = i >> 5;          // 0..33 (i < 34*32)
            int c = i & 31;
            int w = wp - 1;
            float v = 0.0f;
            if (row >= 0 && row < HDIM && w >= 0 && w < WDIM)
                v = X[(((n * HDIM) + row) * WDIM + w) * CH + c];
            Xs[(dh * CH + c) * WPAD + wp] = v;
        }
    }
    __syncthreads();

    const int w = tid & 31;           // output w position
    const int g = tid >> 5;           // filter group 0..7 -> pairs 4g..4g+3 -> f = 8g..8g+7

    const unsigned long long ABSMASK = 0x7FFFFFFF7FFFFFFFULL;

    unsigned long long acc0 = 0ull, acc1 = 0ull, acc2 = 0ull, acc3 = 0ull;

    // Filter pairs viewed as u64: index kk*32 + pidx
    const unsigned long long* Fp = reinterpret_cast<const unsigned long long*>(Fs);

    #pragma unroll
    for (int dh = 0; dh < 3; dh++) {
        #pragma unroll
        for (int dw = 0; dw < 3; dw++) {
            const float* xp = &Xs[(dh * CH) * WPAD + (w + dw)];
            const unsigned long long* fb = Fp + ((dh * 3 + dw) * CH) * 32 + (g * 4);
            #pragma unroll 4
            for (int c = 0; c < CH; c++) {
                unsigned long long xx = pack_dup(xp[c * WPAD]);
                const unsigned long long* fk = fb + c * 32;
                unsigned long long f0 = fk[0];
                unsigned long long f1 = fk[1];
                unsigned long long f2 = fk[2];
                unsigned long long f3 = fk[3];
                unsigned long long d0 = f32x2_add(xx, f0) & ABSMASK;
                unsigned long long d1 = f32x2_add(xx, f1) & ABSMASK;
                unsigned long long d2 = f32x2_add(xx, f2) & ABSMASK;
                unsigned long long d3 = f32x2_add(xx, f3) & ABSMASK;
                acc0 = f32x2_add(acc0, d0);
                acc1 = f32x2_add(acc1, d1);
                acc2 = f32x2_add(acc2, d2);
                acc3 = f32x2_add(acc3, d3);
            }
        }
    }

    // Output: thread writes f = 8g .. 8g+7 at (n,h,w)
    unsigned long long* o = reinterpret_cast<unsigned long long*>(
        out + ((((n * HDIM) + h) * WDIM + w) * F_OUT + g * 8));
    o[0] = acc0;
    o[1] = acc1;
    o[2] = acc2;
    o[3] = acc3;
}

extern "C" void kernel_launch(void* const* d_in, const int* in_sizes, int n_in,
                              void* d_out, int out_size) {
    const float* X = (const float*)d_in[0];
    const float* Fw = (const float*)d_in[1];
    float* out = (float*)d_out;

    cudaFuncSetAttribute(adder_layer_kernel,
                         cudaFuncAttributeMaxDynamicSharedMemorySize, SMEM_BYTES);
    adder_layer_kernel<<<N_IMG * HDIM, 256, SMEM_BYTES>>>(X, Fw, out);
}